// round 13
// baseline (speedup 1.0000x reference)
#include <cuda_runtime.h>
#include <cuda_fp16.h>
#include <cstdint>

#define IN_F   256
#define HID    512
#define OUT_F  2048
#define NHEADS 8
#define BATCH  4096

// ---------------- device scratch ----------------
__device__ int g_off[NHEADS + 1];
__device__ int g_mtoff[NHEADS + 1];
__device__ int g_total_mt;
__device__ int g_perm[BATCH];
__device__ __align__(16) __half g_x[BATCH * IN_F];
__device__ __align__(16) __half g_h[BATCH * HID];
__device__ __align__(16) __half g_w1[NHEADS * IN_F * HID];
__device__ __align__(16) __half g_w2[NHEADS * HID * OUT_F];

// ---------------- helpers ----------------
__device__ __forceinline__ uint32_t packh2(float a, float b) {
    __half2 h = __floats2half2_rn(a, b);
    return *reinterpret_cast<uint32_t*>(&h);
}

#define NX8   (BATCH * IN_F / 8)
#define NW18  (NHEADS * IN_F * HID / 8)
#define NW28  (NHEADS * HID * OUT_F / 8)
#define XW1_BLOCKS ((NX8 + NW18 + 255) / 256)
#define W2_BLOCKS  ((NW28 + 255) / 256)

// block 0: grouping + tile prefix.  blocks 1..: X and W1 fp32 -> fp16.
__global__ void k_prep_xw1(const float* __restrict__ X,
                           const float* __restrict__ W1,
                           const int* __restrict__ idx) {
    if (blockIdx.x == 0) {
        __shared__ int cnt[NHEADS];
        __shared__ int cur[NHEADS];
        int t = threadIdx.x;
        int lane = t & 31;
        if (t < NHEADS) cnt[t] = 0;
        __syncthreads();
        int my[16];
#pragma unroll
        for (int i = 0; i < 16; i++) {
            my[i] = idx[t + i * 256];
            unsigned m = __match_any_sync(0xffffffffu, my[i]);
            if (lane == (__ffs(m) - 1)) atomicAdd(&cnt[my[i]], __popc(m));
        }
        __syncthreads();
        if (t == 0) {
            int s = 0, ts = 0;
            for (int h = 0; h < NHEADS; h++) {
                g_off[h] = s; cur[h] = s; g_mtoff[h] = ts;
                ts += (cnt[h] + 127) / 128;
                s  += cnt[h];
            }
            g_off[NHEADS] = s;
            g_mtoff[NHEADS] = ts;
            g_total_mt = ts;
        }
        __syncthreads();
#pragma unroll
        for (int i = 0; i < 16; i++) {
            unsigned m = __match_any_sync(0xffffffffu, my[i]);
            int leader = __ffs(m) - 1;
            int base = 0;
            if (lane == leader) base = atomicAdd(&cur[my[i]], __popc(m));
            base = __shfl_sync(0xffffffffu, base, leader);
            int rank = __popc(m & ((1u << lane) - 1));
            g_perm[base + rank] = t + i * 256;
        }
        return;
    }
    int i = (blockIdx.x - 1) * 256 + threadIdx.x;
    if (i >= NX8 + NW18) return;
    const float* src;
    __half* dst;
    int j;
    if (i < NX8) { src = X;  dst = g_x;  j = i; }
    else         { src = W1; dst = g_w1; j = i - NX8; }
    float4 v0 = reinterpret_cast<const float4*>(src)[2 * j];
    float4 v1 = reinterpret_cast<const float4*>(src)[2 * j + 1];
    uint4 u = make_uint4(packh2(v0.x, v0.y), packh2(v0.z, v0.w),
                         packh2(v1.x, v1.y), packh2(v1.z, v1.w));
    reinterpret_cast<uint4*>(dst)[j] = u;
}

// W2 fp32 -> fp16 (runs on a forked stream, overlapping the L1 GEMM)
__global__ void k_w2(const float* __restrict__ W2) {
    int j = blockIdx.x * blockDim.x + threadIdx.x;
    if (j >= NW28) return;
    float4 v0 = reinterpret_cast<const float4*>(W2)[2 * j];
    float4 v1 = reinterpret_cast<const float4*>(W2)[2 * j + 1];
    uint4 u = make_uint4(packh2(v0.x, v0.y), packh2(v0.z, v0.w),
                         packh2(v1.x, v1.y), packh2(v1.z, v1.w));
    reinterpret_cast<uint4*>(g_w2)[j] = u;
}

// ---------------- PTX helpers ----------------
__device__ __forceinline__ uint32_t smem_u32(const void* p) {
    uint32_t a;
    asm("{ .reg .u64 t; cvta.to.shared.u64 t, %1; cvt.u32.u64 %0, t; }" : "=r"(a) : "l"(p));
    return a;
}
__device__ __forceinline__ void cp_async16(uint32_t dst, const void* src, bool valid) {
    int sz = valid ? 16 : 0;
    asm volatile("cp.async.ca.shared.global [%0], [%1], 16, %2;"
                 :: "r"(dst), "l"(src), "r"(sz) : "memory");
}
#define CP_COMMIT() asm volatile("cp.async.commit_group;" ::: "memory")
__device__ __forceinline__ void ldsm4(uint32_t* r, uint32_t addr) {
    asm volatile("ldmatrix.sync.aligned.m8n8.x4.shared.b16 {%0,%1,%2,%3}, [%4];"
                 : "=r"(r[0]), "=r"(r[1]), "=r"(r[2]), "=r"(r[3]) : "r"(addr));
}
__device__ __forceinline__ void ldsm4t(uint32_t* r, uint32_t addr) {
    asm volatile("ldmatrix.sync.aligned.m8n8.x4.trans.shared.b16 {%0,%1,%2,%3}, [%4];"
                 : "=r"(r[0]), "=r"(r[1]), "=r"(r[2]), "=r"(r[3]) : "r"(addr));
}
__device__ __forceinline__ void mma16816(float* d, const uint32_t* a, const uint32_t* b) {
    asm volatile("mma.sync.aligned.m16n8k16.row.col.f32.f16.f16.f32 "
                 "{%0,%1,%2,%3}, {%4,%5,%6,%7}, {%8,%9}, {%0,%1,%2,%3};"
                 : "+f"(d[0]), "+f"(d[1]), "+f"(d[2]), "+f"(d[3])
                 : "r"(a[0]), "r"(a[1]), "r"(a[2]), "r"(a[3]), "r"(b[0]), "r"(b[1]));
}

// ---------------- smem layout: K=64 chunks, 3 stages (R11 config) ----------------
#define A_LDB  144
#define B_LDB  272
#define OFF_A  0
#define OFF_B  (128 * A_LDB)
#define STAGE_SZ (128 * A_LDB + 64 * B_LDB)  // 35840
#define NSTAGE 3
#define SMEM_TOTAL (NSTAGE * STAGE_SZ)       // 107520

#define NPERSIST 296

// ---------------- persistent grouped GEMM, single fp16, K=64 chunks ----------------
template <bool L1>
__global__ __launch_bounds__(256, 2)
void gemm_mma(const float* __restrict__ bias, float* __restrict__ Cout)
{
    constexpr int K  = L1 ? IN_F : HID;
    constexpr int N  = L1 ? HID  : OUT_F;
    constexpr int NC = K / 64;
    constexpr int NT = N / 128;

    __shared__ int s_off[NHEADS + 1];
    __shared__ int s_mt[NHEADS + 1];
    extern __shared__ __align__(16) char smem[];

    const int tid = threadIdx.x;
    if (tid < NHEADS + 1) { s_off[tid] = g_off[tid]; s_mt[tid] = g_mtoff[tid]; }
    __syncthreads();

    const int tiles_total = g_total_mt * NT;
    const int bid = blockIdx.x;
    if (bid >= tiles_total) return;
    const int G = gridDim.x;
    const int my_tiles  = (tiles_total - bid + G - 1) / G;
    const int my_chunks = my_tiles * NC;

    const __half* Ap = L1 ? g_x  : g_h;
    const __half* Bp = L1 ? g_w1 : g_w2;

    const uint32_t sb = smem_u32(smem);
    const int wid  = tid >> 5;
    const int lane = tid & 31;
    const int mw = (wid & 3) * 32;
    const int nw = (wid >> 2) * 64;

    auto tile_params = [&](int tt, int& hd, int& mstart, int& m0, int& n0, int& mlim) {
        int mt = tt / NT, nt = tt % NT;
        hd = 0;
#pragma unroll
        for (int i = 1; i < NHEADS; i++) hd += (mt >= s_mt[i]);
        mstart = s_off[hd];
        m0 = (mt - s_mt[hd]) * 128;
        mlim = s_off[hd + 1] - mstart - m0;
        n0 = nt * 128;
    };

    auto prefetch = [&](int j) {
        const int tl = j / NC;
        const int c  = j - tl * NC;
        const int tt = bid + tl * G;
        int hd, mstart, m0, n0, mlim;
        tile_params(tt, hd, mstart, m0, n0, mlim);
        const int k0 = c * 64;
        const uint32_t bo = sb + (uint32_t)(j % NSTAGE) * STAGE_SZ;
#pragma unroll
        for (int jj = 0; jj < 4; jj++) {
            int e = tid + jj * 256;
            int row = e >> 3, q = e & 7;
            bool ok = row < mlim;
            int src = ok ? (L1 ? g_perm[mstart + m0 + row] : (mstart + m0 + row)) : 0;
            uint32_t ad = bo + OFF_A + (uint32_t)(row * A_LDB + q * 16);
            cp_async16(ad, Ap + (size_t)src * K + k0 + q * 8, ok);
        }
#pragma unroll
        for (int jj = 0; jj < 4; jj++) {
            int e = tid + jj * 256;
            int kb = e >> 4, qb = e & 15;
            uint32_t bd = bo + OFF_B + (uint32_t)(kb * B_LDB + qb * 16);
            size_t gb = (size_t)hd * K * N + (size_t)(k0 + kb) * N + n0 + qb * 8;
            cp_async16(bd, Bp + gb, true);
        }
    };

    float acc[2][8][4];
#pragma unroll
    for (int a = 0; a < 2; a++)
#pragma unroll
        for (int b = 0; b < 8; b++)
#pragma unroll
            for (int c = 0; c < 4; c++) acc[a][b][c] = 0.f;

    prefetch(0); CP_COMMIT();
    prefetch(1); CP_COMMIT();

    const int grp = lane >> 3, r = lane & 7;
    const int trow = lane >> 2;
    const int tcol = (lane & 3) * 2;

    for (int j = 0; j < my_chunks; j++) {
        if (j == my_chunks - 1) asm volatile("cp.async.wait_group 0;" ::: "memory");
        else                    asm volatile("cp.async.wait_group 1;" ::: "memory");
        __syncthreads();

        if (j + 2 < my_chunks) {
            prefetch(j + 2);
            CP_COMMIT();
        }

        const uint32_t bo = sb + (uint32_t)(j % NSTAGE) * STAGE_SZ;
#pragma unroll
        for (int ks = 0; ks < 4; ks++) {
            const int kk = ks * 16;
            uint32_t af[2][4];
            uint32_t arow_off = (uint32_t)((mw + (grp & 1) * 8 + r) * A_LDB
                                           + (kk + (grp >> 1) * 8) * 2);
            ldsm4(af[0], bo + OFF_A + arow_off);
            ldsm4(af[1], bo + OFF_A + arow_off + 16 * A_LDB);
            uint32_t bbase = (uint32_t)((kk + (grp & 1) * 8 + r) * B_LDB
                                        + ((grp >> 1) * 8) * 2);
#pragma unroll
            for (int nb = 0; nb < 4; nb++) {
                uint32_t bfr[4];
                ldsm4t(bfr, bo + OFF_B + bbase + (uint32_t)((nw + nb * 16) * 2));
#pragma unroll
                for (int mf = 0; mf < 2; mf++)
#pragma unroll
                    for (int nf = 0; nf < 2; nf++)
                        mma16816(acc[mf][nb * 2 + nf], af[mf], &bfr[nf * 2]);
            }
        }

        if ((j % NC) == NC - 1) {
            const int tt = bid + (j / NC) * G;
            int hd, mstart, m0, n0, mlim;
            tile_params(tt, hd, mstart, m0, n0, mlim);
            const float* bs = bias + (size_t)hd * N + n0;
#pragma unroll
            for (int mf = 0; mf < 2; mf++) {
#pragma unroll
                for (int rr = 0; rr < 2; rr++) {
                    int rloc = mw + mf * 16 + rr * 8 + trow;
                    if (rloc < mlim) {
                        int grow = L1 ? (mstart + m0 + rloc) : g_perm[mstart + m0 + rloc];
#pragma unroll
                        for (int nf = 0; nf < 8; nf++) {
                            int col = nw + nf * 8 + tcol;
                            float2 bv = *reinterpret_cast<const float2*>(&bs[col]);
                            float v0 = acc[mf][nf][rr * 2 + 0] + bv.x;
                            float v1 = acc[mf][nf][rr * 2 + 1] + bv.y;
                            if (L1) {
                                v0 = fmaxf(v0, 0.f);
                                v1 = fmaxf(v1, 0.f);
                                size_t o = (size_t)grow * HID + n0 + col;
                                *reinterpret_cast<uint32_t*>(&g_h[o]) = packh2(v0, v1);
                            } else {
                                *reinterpret_cast<float2*>(
                                    &Cout[(size_t)grow * OUT_F + n0 + col]) = make_float2(v0, v1);
                            }
                        }
                    }
                }
            }
#pragma unroll
            for (int a = 0; a < 2; a++)
#pragma unroll
                for (int b = 0; b < 8; b++)
#pragma unroll
                    for (int c2 = 0; c2 < 4; c2++) acc[a][b][c2] = 0.f;
        }
    }
}

// ---------------- launch ----------------
extern "C" void kernel_launch(void* const* d_in, const int* in_sizes, int n_in,
                              void* d_out, int out_size)
{
    const float* X   = (const float*)d_in[0];
    const int*   idx = (const int*)  d_in[1];
    const float* W1  = (const float*)d_in[2];
    const float* b1  = (const float*)d_in[3];
    const float* W2  = (const float*)d_in[4];
    const float* b2  = (const float*)d_in[5];
    float*       out = (float*)d_out;

    static cudaStream_t s2 = nullptr;
    static cudaEvent_t evFork = nullptr, evJoin = nullptr;
    if (s2 == nullptr) {
        cudaFuncSetAttribute(gemm_mma<true>,  cudaFuncAttributeMaxDynamicSharedMemorySize, SMEM_TOTAL);
        cudaFuncSetAttribute(gemm_mma<false>, cudaFuncAttributeMaxDynamicSharedMemorySize, SMEM_TOTAL);
        cudaStreamCreateWithFlags(&s2, cudaStreamNonBlocking);
        cudaEventCreateWithFlags(&evFork, cudaEventDisableTiming);
        cudaEventCreateWithFlags(&evJoin, cudaEventDisableTiming);
    }

    // main stream: grouping + X/W1 conversion
    k_prep_xw1<<<XW1_BLOCKS + 1, 256>>>(X, W1, idx);

    // fork: W2 conversion on s2, concurrent with L1 GEMM
    cudaEventRecord(evFork, 0);
    cudaStreamWaitEvent(s2, evFork, 0);
    k_w2<<<W2_BLOCKS, 256, 0, s2>>>(W2);

    // L1 GEMM on main stream (needs g_x, g_w1 only)
    gemm_mma<true><<<NPERSIST, 256, SMEM_TOTAL>>>(b1, nullptr);

    // join: L2 GEMM needs g_w2
    cudaEventRecord(evJoin, s2);
    cudaStreamWaitEvent(0, evJoin, 0);
    gemm_mma<false><<<NPERSIST, 256, SMEM_TOTAL>>>(b2, out);
}

// round 14
// speedup vs baseline: 1.0917x; 1.0917x over previous
#include <cuda_runtime.h>
#include <cuda_fp16.h>
#include <cstdint>

#define IN_F   256
#define HID    512
#define OUT_F  2048
#define NHEADS 8
#define BATCH  4096

// ---------------- device scratch ----------------
__device__ int g_off[NHEADS + 1];
__device__ int g_mtoff[NHEADS + 1];
__device__ int g_total_mt;
__device__ int g_perm[BATCH];
__device__ __align__(16) __half g_x[BATCH * IN_F];
__device__ __align__(16) __half g_h[BATCH * HID];
__device__ __align__(16) __half g_w1[NHEADS * IN_F * HID];
__device__ __align__(16) __half g_w2[NHEADS * HID * OUT_F];

// ---------------- helpers ----------------
__device__ __forceinline__ uint32_t packh2(float a, float b) {
    __half2 h = __floats2half2_rn(a, b);
    return *reinterpret_cast<uint32_t*>(&h);
}

#define NX8   (BATCH * IN_F / 8)
#define NW18  (NHEADS * IN_F * HID / 8)
#define NW28  (NHEADS * HID * OUT_F / 8)
#define NSPLIT8 (NX8 + NW18 + NW28)
#define SPLIT_BLOCKS ((NSPLIT8 + 255) / 256)

// block 0: grouping + tile prefix.  blocks 1..: fp32 -> fp16 conversions.
__global__ void k_prep(const float* __restrict__ X,
                       const float* __restrict__ W1,
                       const float* __restrict__ W2,
                       const int* __restrict__ idx) {
    if (blockIdx.x == 0) {
        __shared__ int cnt[NHEADS];
        __shared__ int cur[NHEADS];
        int t = threadIdx.x;
        int lane = t & 31;
        if (t < NHEADS) cnt[t] = 0;
        __syncthreads();
        int my[16];
#pragma unroll
        for (int i = 0; i < 16; i++) {
            my[i] = idx[t + i * 256];
            unsigned m = __match_any_sync(0xffffffffu, my[i]);
            if (lane == (__ffs(m) - 1)) atomicAdd(&cnt[my[i]], __popc(m));
        }
        __syncthreads();
        if (t == 0) {
            int s = 0, ts = 0;
            for (int h = 0; h < NHEADS; h++) {
                g_off[h] = s; cur[h] = s; g_mtoff[h] = ts;
                ts += (cnt[h] + 127) / 128;
                s  += cnt[h];
            }
            g_off[NHEADS] = s;
            g_mtoff[NHEADS] = ts;
            g_total_mt = ts;
        }
        __syncthreads();
#pragma unroll
        for (int i = 0; i < 16; i++) {
            unsigned m = __match_any_sync(0xffffffffu, my[i]);
            int leader = __ffs(m) - 1;
            int base = 0;
            if (lane == leader) base = atomicAdd(&cur[my[i]], __popc(m));
            base = __shfl_sync(0xffffffffu, base, leader);
            int rank = __popc(m & ((1u << lane) - 1));
            g_perm[base + rank] = t + i * 256;
        }
        return;
    }
    int i = (blockIdx.x - 1) * 256 + threadIdx.x;
    if (i >= NSPLIT8) return;
    const float* src;
    __half* dst;
    int j;
    if (i < NX8)             { src = X;  dst = g_x;  j = i; }
    else if (i < NX8 + NW18) { src = W1; dst = g_w1; j = i - NX8; }
    else                     { src = W2; dst = g_w2; j = i - NX8 - NW18; }
    float4 v0 = reinterpret_cast<const float4*>(src)[2 * j];
    float4 v1 = reinterpret_cast<const float4*>(src)[2 * j + 1];
    uint4 u = make_uint4(packh2(v0.x, v0.y), packh2(v0.z, v0.w),
                         packh2(v1.x, v1.y), packh2(v1.z, v1.w));
    reinterpret_cast<uint4*>(dst)[j] = u;
}

// ---------------- PTX helpers ----------------
__device__ __forceinline__ uint32_t smem_u32(const void* p) {
    uint32_t a;
    asm("{ .reg .u64 t; cvta.to.shared.u64 t, %1; cvt.u32.u64 %0, t; }" : "=r"(a) : "l"(p));
    return a;
}
__device__ __forceinline__ void cp_async16(uint32_t dst, const void* src, bool valid) {
    int sz = valid ? 16 : 0;
    asm volatile("cp.async.ca.shared.global [%0], [%1], 16, %2;"
                 :: "r"(dst), "l"(src), "r"(sz) : "memory");
}
#define CP_COMMIT() asm volatile("cp.async.commit_group;" ::: "memory")
__device__ __forceinline__ void ldsm4(uint32_t* r, uint32_t addr) {
    asm volatile("ldmatrix.sync.aligned.m8n8.x4.shared.b16 {%0,%1,%2,%3}, [%4];"
                 : "=r"(r[0]), "=r"(r[1]), "=r"(r[2]), "=r"(r[3]) : "r"(addr));
}
__device__ __forceinline__ void ldsm4t(uint32_t* r, uint32_t addr) {
    asm volatile("ldmatrix.sync.aligned.m8n8.x4.trans.shared.b16 {%0,%1,%2,%3}, [%4];"
                 : "=r"(r[0]), "=r"(r[1]), "=r"(r[2]), "=r"(r[3]) : "r"(addr));
}
__device__ __forceinline__ void mma16816(float* d, const uint32_t* a, const uint32_t* b) {
    asm volatile("mma.sync.aligned.m16n8k16.row.col.f32.f16.f16.f32 "
                 "{%0,%1,%2,%3}, {%4,%5,%6,%7}, {%8,%9}, {%0,%1,%2,%3};"
                 : "+f"(d[0]), "+f"(d[1]), "+f"(d[2]), "+f"(d[3])
                 : "r"(a[0]), "r"(a[1]), "r"(a[2]), "r"(a[3]), "r"(b[0]), "r"(b[1]));
}

// ---------------- smem layout: K=64 chunks, 3 stages ----------------
#define A_LDB  144
#define B_LDB  272
#define OFF_A  0
#define OFF_B  (128 * A_LDB)
#define STAGE_SZ (128 * A_LDB + 64 * B_LDB)  // 35840
#define NSTAGE 3
#define SMEM_TOTAL (NSTAGE * STAGE_SZ)       // 107520

#define NTHREADS 128
#define NPERSIST 296                   // 2 CTAs x 148 SMs

// ---------------- persistent grouped GEMM: 4 warps, 64x64 warp tiles ----------------
template <bool L1>
__global__ __launch_bounds__(NTHREADS, 2)
void gemm_mma(const float* __restrict__ bias, float* __restrict__ Cout)
{
    constexpr int K  = L1 ? IN_F : HID;
    constexpr int N  = L1 ? HID  : OUT_F;
    constexpr int NC = K / 64;
    constexpr int NT = N / 128;

    __shared__ int s_off[NHEADS + 1];
    __shared__ int s_mt[NHEADS + 1];
    extern __shared__ __align__(16) char smem[];

    const int tid = threadIdx.x;
    if (tid < NHEADS + 1) { s_off[tid] = g_off[tid]; s_mt[tid] = g_mtoff[tid]; }
    __syncthreads();

    const int tiles_total = g_total_mt * NT;
    const int bid = blockIdx.x;
    if (bid >= tiles_total) return;
    const int G = gridDim.x;
    const int my_tiles  = (tiles_total - bid + G - 1) / G;
    const int my_chunks = my_tiles * NC;

    const __half* Ap = L1 ? g_x  : g_h;
    const __half* Bp = L1 ? g_w1 : g_w2;

    const uint32_t sb = smem_u32(smem);
    const int wid  = tid >> 5;
    const int lane = tid & 31;
    const int mw = (wid & 1) * 64;     // warp m offset (64 rows)
    const int nw = (wid >> 1) * 64;    // warp n offset (64 cols)

    auto tile_params = [&](int tt, int& hd, int& mstart, int& m0, int& n0, int& mlim) {
        int mt = tt / NT, nt = tt % NT;
        hd = 0;
#pragma unroll
        for (int i = 1; i < NHEADS; i++) hd += (mt >= s_mt[i]);
        mstart = s_off[hd];
        m0 = (mt - s_mt[hd]) * 128;
        mlim = s_off[hd + 1] - mstart - m0;
        n0 = nt * 128;
    };

    auto prefetch = [&](int j) {
        const int tl = j / NC;
        const int c  = j - tl * NC;
        const int tt = bid + tl * G;
        int hd, mstart, m0, n0, mlim;
        tile_params(tt, hd, mstart, m0, n0, mlim);
        const int k0 = c * 64;
        const uint32_t bo = sb + (uint32_t)(j % NSTAGE) * STAGE_SZ;
        // A: 128 rows x 64 fp16 = 1024 uint4 slots, 8 per thread
#pragma unroll
        for (int jj = 0; jj < 8; jj++) {
            int e = tid + jj * NTHREADS;
            int row = e >> 3, q = e & 7;
            bool ok = row < mlim;
            int src = ok ? (L1 ? g_perm[mstart + m0 + row] : (mstart + m0 + row)) : 0;
            uint32_t ad = bo + OFF_A + (uint32_t)(row * A_LDB + q * 16);
            cp_async16(ad, Ap + (size_t)src * K + k0 + q * 8, ok);
        }
        // B: 64 rows x 128 fp16 = 1024 uint4 slots, 8 per thread
#pragma unroll
        for (int jj = 0; jj < 8; jj++) {
            int e = tid + jj * NTHREADS;
            int kb = e >> 4, qb = e & 15;
            uint32_t bd = bo + OFF_B + (uint32_t)(kb * B_LDB + qb * 16);
            size_t gb = (size_t)hd * K * N + (size_t)(k0 + kb) * N + n0 + qb * 8;
            cp_async16(bd, Bp + gb, true);
        }
    };

    float acc[4][8][4];
#pragma unroll
    for (int a = 0; a < 4; a++)
#pragma unroll
        for (int b = 0; b < 8; b++)
#pragma unroll
            for (int c = 0; c < 4; c++) acc[a][b][c] = 0.f;

    prefetch(0); CP_COMMIT();
    prefetch(1); CP_COMMIT();

    const int grp = lane >> 3, r = lane & 7;
    const int trow = lane >> 2;
    const int tcol = (lane & 3) * 2;

    for (int j = 0; j < my_chunks; j++) {
        if (j == my_chunks - 1) asm volatile("cp.async.wait_group 0;" ::: "memory");
        else                    asm volatile("cp.async.wait_group 1;" ::: "memory");
        __syncthreads();

        if (j + 2 < my_chunks) {
            prefetch(j + 2);
            CP_COMMIT();
        }

        const uint32_t bo = sb + (uint32_t)(j % NSTAGE) * STAGE_SZ;
#pragma unroll
        for (int ks = 0; ks < 4; ks++) {
            const int kk = ks * 16;
            // A: 64 rows (4 m16 frags)
            uint32_t af[4][4];
            uint32_t arow_off = (uint32_t)((mw + (grp & 1) * 8 + r) * A_LDB
                                           + (kk + (grp >> 1) * 8) * 2);
#pragma unroll
            for (int mf = 0; mf < 4; mf++)
                ldsm4(af[mf], bo + OFF_A + arow_off + (uint32_t)(mf * 16 * A_LDB));
            // B: 64 cols (8 n8 frags)
            uint32_t bfr[16];
            uint32_t bbase = (uint32_t)((kk + (grp & 1) * 8 + r) * B_LDB
                                        + ((grp >> 1) * 8) * 2);
#pragma unroll
            for (int nb = 0; nb < 4; nb++)
                ldsm4t(&bfr[nb * 4], bo + OFF_B + bbase + (uint32_t)((nw + nb * 16) * 2));
#pragma unroll
            for (int mf = 0; mf < 4; mf++)
#pragma unroll
                for (int nf = 0; nf < 8; nf++)
                    mma16816(acc[mf][nf], af[mf], &bfr[nf * 2]);
        }

        // ---- tile finished -> epilogue ----
        if ((j % NC) == NC - 1) {
            const int tt = bid + (j / NC) * G;
            int hd, mstart, m0, n0, mlim;
            tile_params(tt, hd, mstart, m0, n0, mlim);
            const float* bs = bias + (size_t)hd * N + n0;
#pragma unroll
            for (int mf = 0; mf < 4; mf++) {
#pragma unroll
                for (int rr = 0; rr < 2; rr++) {
                    int rloc = mw + mf * 16 + rr * 8 + trow;
                    if (rloc < mlim) {
                        int grow = L1 ? (mstart + m0 + rloc) : g_perm[mstart + m0 + rloc];
#pragma unroll
                        for (int nf = 0; nf < 8; nf++) {
                            int col = nw + nf * 8 + tcol;
                            float2 bv = *reinterpret_cast<const float2*>(&bs[col]);
                            float v0 = acc[mf][nf][rr * 2 + 0] + bv.x;
                            float v1 = acc[mf][nf][rr * 2 + 1] + bv.y;
                            if (L1) {
                                v0 = fmaxf(v0, 0.f);
                                v1 = fmaxf(v1, 0.f);
                                size_t o = (size_t)grow * HID + n0 + col;
                                *reinterpret_cast<uint32_t*>(&g_h[o]) = packh2(v0, v1);
                            } else {
                                *reinterpret_cast<float2*>(
                                    &Cout[(size_t)grow * OUT_F + n0 + col]) = make_float2(v0, v1);
                            }
                        }
                    }
                }
            }
#pragma unroll
            for (int a = 0; a < 4; a++)
#pragma unroll
                for (int b = 0; b < 8; b++)
#pragma unroll
                    for (int c2 = 0; c2 < 4; c2++) acc[a][b][c2] = 0.f;
        }
    }
}

// ---------------- launch ----------------
extern "C" void kernel_launch(void* const* d_in, const int* in_sizes, int n_in,
                              void* d_out, int out_size)
{
    const float* X   = (const float*)d_in[0];
    const int*   idx = (const int*)  d_in[1];
    const float* W1  = (const float*)d_in[2];
    const float* b1  = (const float*)d_in[3];
    const float* W2  = (const float*)d_in[4];
    const float* b2  = (const float*)d_in[5];
    float*       out = (float*)d_out;

    static bool attr_done = false;
    if (!attr_done) {
        cudaFuncSetAttribute(gemm_mma<true>,  cudaFuncAttributeMaxDynamicSharedMemorySize, SMEM_TOTAL);
        cudaFuncSetAttribute(gemm_mma<false>, cudaFuncAttributeMaxDynamicSharedMemorySize, SMEM_TOTAL);
        attr_done = true;
    }

    k_prep<<<SPLIT_BLOCKS + 1, 256>>>(X, W1, W2, idx);
    gemm_mma<true><<<NPERSIST,  NTHREADS, SMEM_TOTAL>>>(b1, nullptr);
    gemm_mma<false><<<NPERSIST, NTHREADS, SMEM_TOTAL>>>(b2, out);
}

// round 15
// speedup vs baseline: 1.1276x; 1.0329x over previous
#include <cuda_runtime.h>
#include <cuda_fp16.h>
#include <cstdint>

#define IN_F   256
#define HID    512
#define OUT_F  2048
#define NHEADS 8
#define BATCH  4096

// ---------------- device scratch ----------------
__device__ int g_off[NHEADS + 1];
__device__ int g_mtoff[NHEADS + 1];
__device__ int g_total_mt;
__device__ int g_perm[BATCH];
__device__ __align__(16) __half g_x[BATCH * IN_F];
__device__ __align__(16) __half g_h[BATCH * HID];
__device__ __align__(16) __half g_w1[NHEADS * IN_F * HID];
__device__ __align__(16) __half g_w2[NHEADS * HID * OUT_F];

// ---------------- helpers ----------------
__device__ __forceinline__ uint32_t packh2(float a, float b) {
    __half2 h = __floats2half2_rn(a, b);
    return *reinterpret_cast<uint32_t*>(&h);
}

#define NX8   (BATCH * IN_F / 8)
#define NW18  (NHEADS * IN_F * HID / 8)
#define NW28  (NHEADS * HID * OUT_F / 8)
#define NSPLIT8 (NX8 + NW18 + NW28)
#define SPLIT_BLOCKS ((NSPLIT8 + 255) / 256)

// block 0: grouping + tile prefix.  blocks 1..: fp32 -> fp16 conversions.
__global__ void k_prep(const float* __restrict__ X,
                       const float* __restrict__ W1,
                       const float* __restrict__ W2,
                       const int* __restrict__ idx) {
    if (blockIdx.x == 0) {
        __shared__ int cnt[NHEADS];
        __shared__ int cur[NHEADS];
        int t = threadIdx.x;
        int lane = t & 31;
        if (t < NHEADS) cnt[t] = 0;
        __syncthreads();
        int my[16];
#pragma unroll
        for (int i = 0; i < 16; i++) {
            my[i] = idx[t + i * 256];
            unsigned m = __match_any_sync(0xffffffffu, my[i]);
            if (lane == (__ffs(m) - 1)) atomicAdd(&cnt[my[i]], __popc(m));
        }
        __syncthreads();
        if (t == 0) {
            int s = 0, ts = 0;
            for (int h = 0; h < NHEADS; h++) {
                g_off[h] = s; cur[h] = s; g_mtoff[h] = ts;
                ts += (cnt[h] + 127) / 128;
                s  += cnt[h];
            }
            g_off[NHEADS] = s;
            g_mtoff[NHEADS] = ts;
            g_total_mt = ts;
        }
        __syncthreads();
#pragma unroll
        for (int i = 0; i < 16; i++) {
            unsigned m = __match_any_sync(0xffffffffu, my[i]);
            int leader = __ffs(m) - 1;
            int base = 0;
            if (lane == leader) base = atomicAdd(&cur[my[i]], __popc(m));
            base = __shfl_sync(0xffffffffu, base, leader);
            int rank = __popc(m & ((1u << lane) - 1));
            g_perm[base + rank] = t + i * 256;
        }
        return;
    }
    int i = (blockIdx.x - 1) * 256 + threadIdx.x;
    if (i >= NSPLIT8) return;
    const float* src;
    __half* dst;
    int j;
    if (i < NX8)             { src = X;  dst = g_x;  j = i; }
    else if (i < NX8 + NW18) { src = W1; dst = g_w1; j = i - NX8; }
    else                     { src = W2; dst = g_w2; j = i - NX8 - NW18; }
    float4 v0 = reinterpret_cast<const float4*>(src)[2 * j];
    float4 v1 = reinterpret_cast<const float4*>(src)[2 * j + 1];
    uint4 u = make_uint4(packh2(v0.x, v0.y), packh2(v0.z, v0.w),
                         packh2(v1.x, v1.y), packh2(v1.z, v1.w));
    reinterpret_cast<uint4*>(dst)[j] = u;
}

// ---------------- PTX helpers ----------------
__device__ __forceinline__ uint32_t smem_u32(const void* p) {
    uint32_t a;
    asm("{ .reg .u64 t; cvta.to.shared.u64 t, %1; cvt.u32.u64 %0, t; }" : "=r"(a) : "l"(p));
    return a;
}
__device__ __forceinline__ void cp_async16(uint32_t dst, const void* src, bool valid) {
    int sz = valid ? 16 : 0;
    asm volatile("cp.async.ca.shared.global [%0], [%1], 16, %2;"
                 :: "r"(dst), "l"(src), "r"(sz) : "memory");
}
#define CP_COMMIT() asm volatile("cp.async.commit_group;" ::: "memory")
__device__ __forceinline__ void ldsm4(uint32_t* r, uint32_t addr) {
    asm volatile("ldmatrix.sync.aligned.m8n8.x4.shared.b16 {%0,%1,%2,%3}, [%4];"
                 : "=r"(r[0]), "=r"(r[1]), "=r"(r[2]), "=r"(r[3]) : "r"(addr));
}
__device__ __forceinline__ void ldsm4t(uint32_t* r, uint32_t addr) {
    asm volatile("ldmatrix.sync.aligned.m8n8.x4.trans.shared.b16 {%0,%1,%2,%3}, [%4];"
                 : "=r"(r[0]), "=r"(r[1]), "=r"(r[2]), "=r"(r[3]) : "r"(addr));
}
__device__ __forceinline__ void mma16816(float* d, const uint32_t* a, const uint32_t* b) {
    asm volatile("mma.sync.aligned.m16n8k16.row.col.f32.f16.f16.f32 "
                 "{%0,%1,%2,%3}, {%4,%5,%6,%7}, {%8,%9}, {%0,%1,%2,%3};"
                 : "+f"(d[0]), "+f"(d[1]), "+f"(d[2]), "+f"(d[3])
                 : "r"(a[0]), "r"(a[1]), "r"(a[2]), "r"(a[3]), "r"(b[0]), "r"(b[1]));
}

// ---------------- smem layout: K=64 chunks, 3 stages ----------------
#define A_LDB  144
#define B_LDB  272
#define OFF_A  0
#define OFF_B  (128 * A_LDB)
#define STAGE_SZ (128 * A_LDB + 64 * B_LDB)  // 35840
#define NSTAGE 3
#define SMEM_TOTAL (NSTAGE * STAGE_SZ)       // 107520

#define NTHREADS 128
#define NPERSIST 296                   // 2 CTAs x 148 SMs

// ---------------- persistent grouped GEMM: 4 warps, 64x64 warp tiles,
// fragment double-buffering across ks steps ----------------
template <bool L1>
__global__ __launch_bounds__(NTHREADS, 2)
void gemm_mma(const float* __restrict__ bias, float* __restrict__ Cout)
{
    constexpr int K  = L1 ? IN_F : HID;
    constexpr int N  = L1 ? HID  : OUT_F;
    constexpr int NC = K / 64;
    constexpr int NT = N / 128;

    __shared__ int s_off[NHEADS + 1];
    __shared__ int s_mt[NHEADS + 1];
    extern __shared__ __align__(16) char smem[];

    const int tid = threadIdx.x;
    if (tid < NHEADS + 1) { s_off[tid] = g_off[tid]; s_mt[tid] = g_mtoff[tid]; }
    __syncthreads();

    const int tiles_total = g_total_mt * NT;
    const int bid = blockIdx.x;
    if (bid >= tiles_total) return;
    const int G = gridDim.x;
    const int my_tiles  = (tiles_total - bid + G - 1) / G;
    const int my_chunks = my_tiles * NC;

    const __half* Ap = L1 ? g_x  : g_h;
    const __half* Bp = L1 ? g_w1 : g_w2;

    const uint32_t sb = smem_u32(smem);
    const int wid  = tid >> 5;
    const int lane = tid & 31;
    const int mw = (wid & 1) * 64;     // warp m offset
    const int nw = (wid >> 1) * 64;    // warp n offset

    auto tile_params = [&](int tt, int& hd, int& mstart, int& m0, int& n0, int& mlim) {
        int mt = tt / NT, nt = tt % NT;
        hd = 0;
#pragma unroll
        for (int i = 1; i < NHEADS; i++) hd += (mt >= s_mt[i]);
        mstart = s_off[hd];
        m0 = (mt - s_mt[hd]) * 128;
        mlim = s_off[hd + 1] - mstart - m0;
        n0 = nt * 128;
    };

    auto prefetch = [&](int j) {
        const int tl = j / NC;
        const int c  = j - tl * NC;
        const int tt = bid + tl * G;
        int hd, mstart, m0, n0, mlim;
        tile_params(tt, hd, mstart, m0, n0, mlim);
        const int k0 = c * 64;
        const uint32_t bo = sb + (uint32_t)(j % NSTAGE) * STAGE_SZ;
#pragma unroll
        for (int jj = 0; jj < 8; jj++) {
            int e = tid + jj * NTHREADS;
            int row = e >> 3, q = e & 7;
            bool ok = row < mlim;
            int src = ok ? (L1 ? g_perm[mstart + m0 + row] : (mstart + m0 + row)) : 0;
            uint32_t ad = bo + OFF_A + (uint32_t)(row * A_LDB + q * 16);
            cp_async16(ad, Ap + (size_t)src * K + k0 + q * 8, ok);
        }
#pragma unroll
        for (int jj = 0; jj < 8; jj++) {
            int e = tid + jj * NTHREADS;
            int kb = e >> 4, qb = e & 15;
            uint32_t bd = bo + OFF_B + (uint32_t)(kb * B_LDB + qb * 16);
            size_t gb = (size_t)hd * K * N + (size_t)(k0 + kb) * N + n0 + qb * 8;
            cp_async16(bd, Bp + gb, true);
        }
    };

    float acc[4][8][4];
#pragma unroll
    for (int a = 0; a < 4; a++)
#pragma unroll
        for (int b = 0; b < 8; b++)
#pragma unroll
            for (int c = 0; c < 4; c++) acc[a][b][c] = 0.f;

    prefetch(0); CP_COMMIT();
    prefetch(1); CP_COMMIT();

    const int grp = lane >> 3, r = lane & 7;
    const int trow = lane >> 2;
    const int tcol = (lane & 3) * 2;
    // per-warp fragment base offsets (ks-invariant parts)
    const uint32_t a_off0 = (uint32_t)((mw + (grp & 1) * 8 + r) * A_LDB
                                       + ((grp >> 1) * 8) * 2);
    const uint32_t b_off0 = (uint32_t)(((grp & 1) * 8 + r) * B_LDB
                                       + ((grp >> 1) * 8) * 2);

    // double-buffered fragments
    uint32_t af[2][4][4];
    uint32_t bf[2][16];

    for (int j = 0; j < my_chunks; j++) {
        if (j == my_chunks - 1) asm volatile("cp.async.wait_group 0;" ::: "memory");
        else                    asm volatile("cp.async.wait_group 1;" ::: "memory");
        __syncthreads();

        if (j + 2 < my_chunks) {
            prefetch(j + 2);
            CP_COMMIT();
        }

        const uint32_t bo = sb + (uint32_t)(j % NSTAGE) * STAGE_SZ;

        // load fragments for ks=0 into buffer 0
        {
            uint32_t aoff = bo + OFF_A + a_off0;
            uint32_t boff = bo + OFF_B + b_off0;
#pragma unroll
            for (int mf = 0; mf < 4; mf++)
                ldsm4(af[0][mf], aoff + (uint32_t)(mf * 16 * A_LDB));
#pragma unroll
            for (int nb = 0; nb < 4; nb++)
                ldsm4t(&bf[0][nb * 4], boff + (uint32_t)((nw + nb * 16) * 2));
        }

#pragma unroll
        for (int ks = 0; ks < 4; ks++) {
            const int cur = ks & 1;
            // prefetch fragments for ks+1 into the other buffer (overlaps MMAs)
            if (ks < 3) {
                const int kk = (ks + 1) * 16;
                uint32_t aoff = bo + OFF_A + a_off0 + (uint32_t)(kk * 2);
                uint32_t boff = bo + OFF_B + b_off0 + (uint32_t)(kk * B_LDB);
#pragma unroll
                for (int mf = 0; mf < 4; mf++)
                    ldsm4(af[cur ^ 1][mf], aoff + (uint32_t)(mf * 16 * A_LDB));
#pragma unroll
                for (int nb = 0; nb < 4; nb++)
                    ldsm4t(&bf[cur ^ 1][nb * 4], boff + (uint32_t)((nw + nb * 16) * 2));
            }
#pragma unroll
            for (int mf = 0; mf < 4; mf++)
#pragma unroll
                for (int nf = 0; nf < 8; nf++)
                    mma16816(acc[mf][nf], af[cur][mf], &bf[cur][nf * 2]);
        }

        // ---- tile finished -> epilogue ----
        if ((j % NC) == NC - 1) {
            const int tt = bid + (j / NC) * G;
            int hd, mstart, m0, n0, mlim;
            tile_params(tt, hd, mstart, m0, n0, mlim);
            const float* bs = bias + (size_t)hd * N + n0;
#pragma unroll
            for (int mf = 0; mf < 4; mf++) {
#pragma unroll
                for (int rr = 0; rr < 2; rr++) {
                    int rloc = mw + mf * 16 + rr * 8 + trow;
                    if (rloc < mlim) {
                        int grow = L1 ? (mstart + m0 + rloc) : g_perm[mstart + m0 + rloc];
#pragma unroll
                        for (int nf = 0; nf < 8; nf++) {
                            int col = nw + nf * 8 + tcol;
                            float2 bv = *reinterpret_cast<const float2*>(&bs[col]);
                            float v0 = acc[mf][nf][rr * 2 + 0] + bv.x;
                            float v1 = acc[mf][nf][rr * 2 + 1] + bv.y;
                            if (L1) {
                                v0 = fmaxf(v0, 0.f);
                                v1 = fmaxf(v1, 0.f);
                                size_t o = (size_t)grow * HID + n0 + col;
                                *reinterpret_cast<uint32_t*>(&g_h[o]) = packh2(v0, v1);
                            } else {
                                *reinterpret_cast<float2*>(
                                    &Cout[(size_t)grow * OUT_F + n0 + col]) = make_float2(v0, v1);
                            }
                        }
                    }
                }
            }
#pragma unroll
            for (int a = 0; a < 4; a++)
#pragma unroll
                for (int b = 0; b < 8; b++)
#pragma unroll
                    for (int c2 = 0; c2 < 4; c2++) acc[a][b][c2] = 0.f;
        }
    }
}

// ---------------- launch ----------------
extern "C" void kernel_launch(void* const* d_in, const int* in_sizes, int n_in,
                              void* d_out, int out_size)
{
    const float* X   = (const float*)d_in[0];
    const int*   idx = (const int*)  d_in[1];
    const float* W1  = (const float*)d_in[2];
    const float* b1  = (const float*)d_in[3];
    const float* W2  = (const float*)d_in[4];
    const float* b2  = (const float*)d_in[5];
    float*       out = (float*)d_out;

    static bool attr_done = false;
    if (!attr_done) {
        cudaFuncSetAttribute(gemm_mma<true>,  cudaFuncAttributeMaxDynamicSharedMemorySize, SMEM_TOTAL);
        cudaFuncSetAttribute(gemm_mma<false>, cudaFuncAttributeMaxDynamicSharedMemorySize, SMEM_TOTAL);
        attr_done = true;
    }

    k_prep<<<SPLIT_BLOCKS + 1, 256>>>(X, W1, W2, idx);
    gemm_mma<true><<<NPERSIST,  NTHREADS, SMEM_TOTAL>>>(b1, nullptr);
    gemm_mma<false><<<NPERSIST, NTHREADS, SMEM_TOTAL>>>(b2, out);
}